// round 2
// baseline (speedup 1.0000x reference)
#include <cuda_runtime.h>
#include <math.h>

#define BB 64
#define TT 512
#define II 256
#define OO 1024
#define MM 8
#define IMM 2048
#define KA (II + OO)     // 1280
#define KR (II + IMM)    // 2304
#define NBLK 129
#define NGEMM 128
#define NT 256
#define KSPLIT_REC 12
#define KSPLIT_ACT 8
#define DYN_SMEM 73728   // max(gemm 20KB, gate 72KB)

// ---------------- device scratch (no runtime allocation allowed) ------------
__device__ float g_Aact[BB * KA];              // [b][ xi(256) | h(1024) ]
__device__ float g_Arec[BB * KR];              // [b][ xi(256) | x_pred(2048) ]
__device__ float g_Pact[KSPLIT_ACT * BB * OO];   // split-K partials (acts)
__device__ float g_Prec[KSPLIT_REC * BB * IMM];  // split-K partials (acts_rec)
__device__ float g_gate[BB * MM];
__device__ float g_mp[BB * MM];
__device__ volatile unsigned g_gen;
__device__ unsigned g_cnt;

// ---------------- grid-wide barrier (all 129 CTAs resident) ------------------
__device__ __forceinline__ void grid_sync() {
    __syncthreads();
    if (threadIdx.x == 0) {
        __threadfence();
        unsigned gen = g_gen;
        if (atomicAdd(&g_cnt, 1u) == (unsigned)(NBLK - 1)) {
            g_cnt = 0u;
            __threadfence();
            g_gen = gen + 1u;
        } else {
            while (g_gen == gen) { __nanosleep(20); }
            __threadfence();
        }
    }
    __syncthreads();
}

// ---------------- packed f32x2 helpers ---------------------------------------
__device__ __forceinline__ unsigned long long splat2(float v) {
    unsigned long long r;
    asm("mov.b64 %0, {%1, %1};" : "=l"(r) : "f"(v));
    return r;
}
__device__ __forceinline__ void ffma2(unsigned long long& d, unsigned long long a,
                                      unsigned long long b) {
    asm("fma.rn.f32x2 %0, %1, %2, %0;" : "+l"(d) : "l"(a), "l"(b));
}
__device__ __forceinline__ float2 unpack2(unsigned long long v) {
    float2 r;
    asm("mov.b64 {%0, %1}, %2;" : "=f"(r.x), "=f"(r.y) : "l"(v));
    return r;
}

// ---------------- 64x256-tile GEMM, split-K chunk, f32x2 math ----------------
// P[b][col0+c] += sum_{k in [k0, k0+16*nsub)} A[b][k] * W(col,k)
// W(col,k) = W1[col*ld1 + k] if k < II else W2[col*ld2 + (k-II)].
__device__ __forceinline__ void gemm_unit(
    const float* __restrict__ A, int lda,
    const float* __restrict__ W1, int ld1,
    const float* __restrict__ W2, int ld2,
    int col0, int k0, int nsub,
    float* __restrict__ P, int NC, float* dynsh)
{
    float* sA = dynsh;              // [16][64]
    float* sB = dynsh + 16 * 64;    // [16][256]
    const int tid = threadIdx.x;
    const int lane = tid & 31, wp = tid >> 5;
    const int ab = tid & 63, ak = (tid >> 6) << 2;
    const int j = col0 + tid;       // W row this thread loads

    unsigned long long acc[8][4];
#pragma unroll
    for (int p = 0; p < 8; p++)
#pragma unroll
        for (int q = 0; q < 4; q++) acc[p][q] = 0ull;

    float4 b0, b1, b2, b3, aq;
    {
        int kb = k0;
        const float* src = (kb < II) ? (W1 + (size_t)j * ld1 + kb)
                                     : (W2 + (size_t)j * ld2 + (kb - II));
        b0 = __ldg((const float4*)(src + 0));
        b1 = __ldg((const float4*)(src + 4));
        b2 = __ldg((const float4*)(src + 8));
        b3 = __ldg((const float4*)(src + 12));
        aq = __ldcg((const float4*)(A + (size_t)ab * lda + kb + ak));
    }

    for (int s = 0; s < nsub; s++) {
        sB[0*256+tid]=b0.x; sB[1*256+tid]=b0.y; sB[2*256+tid]=b0.z; sB[3*256+tid]=b0.w;
        sB[4*256+tid]=b1.x; sB[5*256+tid]=b1.y; sB[6*256+tid]=b1.z; sB[7*256+tid]=b1.w;
        sB[8*256+tid]=b2.x; sB[9*256+tid]=b2.y; sB[10*256+tid]=b2.z; sB[11*256+tid]=b2.w;
        sB[12*256+tid]=b3.x; sB[13*256+tid]=b3.y; sB[14*256+tid]=b3.z; sB[15*256+tid]=b3.w;
        sA[(ak+0)*64+ab]=aq.x; sA[(ak+1)*64+ab]=aq.y;
        sA[(ak+2)*64+ab]=aq.z; sA[(ak+3)*64+ab]=aq.w;
        __syncthreads();

        if (s + 1 < nsub) {     // prefetch next chunk under compute
            int kb = k0 + (s + 1) * 16;
            const float* src = (kb < II) ? (W1 + (size_t)j * ld1 + kb)
                                         : (W2 + (size_t)j * ld2 + (kb - II));
            b0 = __ldg((const float4*)(src + 0));
            b1 = __ldg((const float4*)(src + 4));
            b2 = __ldg((const float4*)(src + 8));
            b3 = __ldg((const float4*)(src + 12));
            aq = __ldcg((const float4*)(A + (size_t)ab * lda + kb + ak));
        }

#pragma unroll
        for (int k = 0; k < 16; k++) {
            float4 a0 = *(const float4*)(sA + k * 64 + wp * 8);
            float4 a1 = *(const float4*)(sA + k * 64 + wp * 8 + 4);
            unsigned long long as[8];
            as[0]=splat2(a0.x); as[1]=splat2(a0.y); as[2]=splat2(a0.z); as[3]=splat2(a0.w);
            as[4]=splat2(a1.x); as[5]=splat2(a1.y); as[6]=splat2(a1.z); as[7]=splat2(a1.w);
            const ulonglong2* wb = (const ulonglong2*)(sB + k * 256 + lane * 8);
            ulonglong2 w01 = wb[0];
            ulonglong2 w23 = wb[1];
#pragma unroll
            for (int p = 0; p < 8; p++) {
                ffma2(acc[p][0], as[p], w01.x);
                ffma2(acc[p][1], as[p], w01.y);
                ffma2(acc[p][2], as[p], w23.x);
                ffma2(acc[p][3], as[p], w23.y);
            }
        }
        __syncthreads();
    }

#pragma unroll
    for (int p = 0; p < 8; p++) {
        int b = wp * 8 + p;
        float* dst = P + (size_t)b * NC + col0 + lane * 8;
#pragma unroll
        for (int q = 0; q < 4; q++) {
            float2 v = unpack2(acc[p][q]);
            *(float2*)(dst + 2 * q) = v;
        }
    }
}

// ---------------- persistent kernel ------------------------------------------
__global__ void __launch_bounds__(NT, 1)
cwrnn_kernel(const float* __restrict__ x, const float* __restrict__ W_in,
             const float* __restrict__ b_in, const float* __restrict__ W_h,
             const float* __restrict__ W_ir, const float* __restrict__ b_ir,
             const float* __restrict__ W_hr, const float* __restrict__ periods,
             const float* __restrict__ shifts, float* __restrict__ out)
{
    extern __shared__ float dynsh[];
    const int bid = blockIdx.x, tid = threadIdx.x;
    float* out_ys = out;
    float* out_hf = out + (size_t)BB * TT * OO;
    float* out_ps = out_hf + BB * OO;

    // init carries: [ xi(0) | zeros ]
    for (int idx = bid * NT + tid; idx < BB * KA; idx += NBLK * NT) {
        int b = idx / KA, k = idx - b * KA;
        g_Aact[idx] = (k < II) ? x[(size_t)b * TT * II + k] : 0.f;
    }
    for (int idx = bid * NT + tid; idx < BB * KR; idx += NBLK * NT) {
        int b = idx / KR, k = idx - b * KR;
        g_Arec[idx] = (k < II) ? x[(size_t)b * TT * II + k] : 0.f;
    }
    grid_sync();

    for (int t = 0; t < TT; t++) {
        // ===== phase A: GEMM partials (CTA 0..127) || softmax gate (CTA 128) =
        if (bid < 96) {
            int nt_ = bid / KSPLIT_REC, ks = bid - nt_ * KSPLIT_REC;
            gemm_unit(g_Arec, KR, W_ir, II, W_hr, IMM, nt_ * 256, ks * 192, 12,
                      g_Prec + (size_t)ks * BB * IMM, IMM, dynsh);
        } else if (bid < NGEMM) {
            int v = bid - 96;
            int nt_ = v / KSPLIT_ACT, ks = v - nt_ * KSPLIT_ACT;
            gemm_unit(g_Aact, KA, W_in, II, W_h, OO, nt_ * 256, ks * 160, 10,
                      g_Pact + (size_t)ks * BB * OO, OO, dynsh);
        } else {
            float* s_lse = dynsh;            // [2048]
            float* s_xi  = dynsh + IMM;      // [64*256]
            for (int idx = tid; idx < BB * II; idx += NT) {
                int b = idx >> 8, i = idx & (II - 1);
                s_xi[idx] = __ldcg(&g_Arec[b * KR + i]);
            }
            for (int col = tid; col < IMM; col += NT) {
                float r[BB];
#pragma unroll
                for (int b = 0; b < BB; b++)
                    r[b] = __ldcg(&g_Arec[b * KR + II + col]);
                float mx = r[0];
#pragma unroll
                for (int b = 1; b < BB; b++) mx = fmaxf(mx, r[b]);
                float sum = 0.f;
#pragma unroll
                for (int b = 0; b < BB; b++) sum += expf(r[b] - mx);
                s_lse[col] = mx + logf(sum);
            }
            __syncthreads();
            const int wp = tid >> 5, lane = tid & 31;
            for (int u = wp; u < BB * MM; u += (NT / 32)) {
                int b = u >> 3, m = u & 7;
                const float* xp = &g_Arec[b * KR + II + m * II];
                float s = 0.f;
                for (int i = lane; i < II; i += 32)
                    s += (__ldcg(&xp[i]) - s_lse[m * II + i]) * s_xi[b * II + i];
#pragma unroll
                for (int off = 16; off > 0; off >>= 1)
                    s += __shfl_xor_sync(0xffffffffu, s, off);
                if (lane == 0) {
                    float mp = s * (1.f / (float)II) * periods[m];
                    g_mp[u] = mp;
                    g_gate[u] = (sinf((float)t * mp + shifts[m]) + 1.f) * 0.5f;
                }
            }
        }
        grid_sync();

        // ===== phase B: reduce split-K, tanh, gate blend, write outputs ======
        const int TOTB = BB * IMM + BB * OO;
        for (int idx = bid * NT + tid; idx < TOTB; idx += NBLK * NT) {
            if (idx < BB * IMM) {
                int b = idx >> 11, jj = idx & (IMM - 1);
                float s = b_ir[jj];
#pragma unroll
                for (int ks = 0; ks < KSPLIT_REC; ks++)
                    s += __ldcg(&g_Prec[((size_t)ks * BB + b) * IMM + jj]);
                g_Arec[b * KR + II + jj] = tanhf(s);   // x_pred(t+1)
            } else {
                int i2 = idx - BB * IMM;
                int b = i2 >> 10, o = i2 & (OO - 1);
                float s = b_in[o];
#pragma unroll
                for (int ks = 0; ks < KSPLIT_ACT; ks++)
                    s += __ldcg(&g_Pact[((size_t)ks * BB + b) * OO + o]);
                float a = tanhf(s);
                float g = __ldcg(&g_gate[b * MM + (o >> 7)]);
                float h = __ldcg(&g_Aact[b * KA + II + o]);
                float y = (1.f - g) * a + g * h;
                out_ys[((size_t)b * TT + t) * OO + o] = y;
                g_Aact[b * KA + II + o] = y;           // h(t+1)
                if (t == TT - 1) out_hf[b * OO + o] = y;
            }
        }
        for (int idx = bid * NT + tid; idx < BB * MM; idx += NBLK * NT)
            out_ps[((size_t)(idx >> 3) * TT + t) * MM + (idx & 7)] = __ldcg(&g_mp[idx]);
        if (t + 1 < TT) {
            for (int idx = bid * NT + tid; idx < BB * II; idx += NBLK * NT) {
                int b = idx >> 8, k = idx & (II - 1);
                float v = x[((size_t)b * TT + (t + 1)) * II + k];
                g_Aact[b * KA + k] = v;
                g_Arec[b * KR + k] = v;
            }
        }
        grid_sync();
    }
}

extern "C" void kernel_launch(void* const* d_in, const int* in_sizes, int n_in,
                              void* d_out, int out_size) {
    (void)in_sizes; (void)n_in; (void)out_size;
    const float* x       = (const float*)d_in[0];
    const float* W_in    = (const float*)d_in[1];
    const float* b_in    = (const float*)d_in[2];
    const float* W_h     = (const float*)d_in[3];
    const float* W_ir    = (const float*)d_in[4];
    const float* b_ir    = (const float*)d_in[5];
    const float* W_hr    = (const float*)d_in[6];
    const float* periods = (const float*)d_in[7];
    const float* shifts  = (const float*)d_in[8];
    float* out = (float*)d_out;

    cudaFuncSetAttribute(cwrnn_kernel,
                         cudaFuncAttributeMaxDynamicSharedMemorySize, DYN_SMEM);
    cwrnn_kernel<<<NBLK, NT, DYN_SMEM>>>(x, W_in, b_in, W_h, W_ir, b_ir, W_hr,
                                         periods, shifts, out);
}

// round 3
// speedup vs baseline: 1.3741x; 1.3741x over previous
#include <cuda_runtime.h>
#include <math.h>

#define BB 64
#define TT 512
#define II 256
#define OO 1024
#define MM 8
#define IMM 2048
#define NBLK 148
#define NGEMM 128
#define NREC 96
#define NGATE 16
#define NT 512
#define KSPLIT_REC 12
#define KSPLIT_ACT 8
#define DYN_SMEM (16*64*4 + 16*256*4)   // sA + sB = 20480 B

// ---------------- persistent device state ------------------------------------
__device__ float g_H[BB * OO];                   // h carry
__device__ float g_XP[BB * IMM];                 // x_pred carry
__device__ float g_Pact[KSPLIT_ACT * BB * OO];   // split-K partials (acts)
__device__ float g_Prec[KSPLIT_REC * BB * IMM];  // split-K partials (acts_rec)
__device__ float g_lse[IMM];
__device__ float g_gate[BB * MM];
__device__ float g_mp[BB * MM];
__device__ volatile unsigned g_arr[NBLK];        // per-CTA arrival flags
__device__ volatile unsigned g_gen;              // global release generation
__device__ volatile unsigned g_garr[NGATE];      // gate mini-barrier flags
__device__ volatile unsigned g_ggen;

// ---------------- flag-based grid barrier (monotonic, replay-safe) -----------
__device__ __forceinline__ void grid_barrier(unsigned target) {
    const int bid = blockIdx.x, tid = threadIdx.x;
    __syncthreads();
    if (tid == 0) { __threadfence(); g_arr[bid] = target; }
    if (bid == NGEMM) {          // releaser = first gate CTA
        if (tid < NBLK) { while ((int)(g_arr[tid] - target) < 0) {} }
        __threadfence();
        __syncthreads();
        if (tid == 0) { g_gen = target; }
        __syncthreads();
    } else {
        if (tid == 0) { while ((int)(g_gen - target) < 0) {} __threadfence(); }
        __syncthreads();
    }
}

// ---------------- packed f32x2 helpers ---------------------------------------
__device__ __forceinline__ unsigned long long splat2(float v) {
    unsigned long long r;
    asm("mov.b64 %0, {%1, %1};" : "=l"(r) : "f"(v));
    return r;
}
__device__ __forceinline__ void ffma2(unsigned long long& d, unsigned long long a,
                                      unsigned long long b) {
    asm("fma.rn.f32x2 %0, %1, %2, %0;" : "+l"(d) : "l"(a), "l"(b));
}
__device__ __forceinline__ float2 unpack2(unsigned long long v) {
    float2 r;
    asm("mov.b64 {%0, %1}, %2;" : "=f"(r.x), "=f"(r.y) : "l"(v));
    return r;
}

// ---------------- 64x256-tile GEMM, one split-K chunk ------------------------
// P[b][col0+c] = sum_{k in [k0, k0+16*nsub)} A[b][k] * W(col,k)
// A[b][k] = xb[b*xs + k]            (k <  II)   (current input slice, read-only)
//         = cb[b*cs + (k-II)]       (k >= II)   (carry, written by other SMs -> ldcg)
// W(c,k)  = W1[c*ld1 + k] (k<II) else W2[c*ld2 + (k-II)]
__device__ __forceinline__ void gemm_unit(
    const float* xb, int xs, const float* cb, int cs,
    const float* __restrict__ W1, int ld1,
    const float* __restrict__ W2, int ld2,
    int col0, int k0, int nsub,
    float* __restrict__ P, int NC, float* dynsh)
{
    float* sA = dynsh;              // [16][64]  k-major
    float* sB = dynsh + 16 * 64;    // [16][256] k-major
    const int tid = threadIdx.x;
    const int wid = tid >> 5, lane = tid & 31;
    const int bg = wid >> 1;                 // batch group 0..7 (8 batches)
    const int cg = (wid & 1) * 32 + lane;    // col group 0..63 (4 cols)
    const int jc = tid & 255;                // sB loader col
    const int kh = (tid >> 8) * 8;           // sB loader k-offset (0 or 8)
    const int row = tid & 63;                // sA loader row (tid<256)
    const int kq = ((tid >> 6) & 3) * 4;     // sA loader k-offset

    unsigned long long acc[4][4];            // [col c][batch pair p]
#pragma unroll
    for (int c = 0; c < 4; c++)
#pragma unroll
        for (int p = 0; p < 4; p++) acc[c][p] = 0ull;

    const int j = col0 + jc;
    float wbuf[8]; float4 abuf;
    {   // prefetch chunk 0
        const int kb = k0;
        const float* ws = ((kb < II) ? (W1 + (size_t)j * ld1 + kb)
                                     : (W2 + (size_t)j * ld2 + (kb - II))) + kh;
        *(float4*)&wbuf[0] = __ldg((const float4*)ws);
        *(float4*)&wbuf[4] = __ldg((const float4*)(ws + 4));
        if (tid < 256) {
            const float* as = (kb < II) ? (xb + row * xs + kb + kq)
                                        : (cb + row * cs + (kb - II) + kq);
            abuf = __ldcg((const float4*)as);
        }
    }

    for (int s = 0; s < nsub; s++) {
#pragma unroll
        for (int i = 0; i < 8; i++) sB[(kh + i) * 256 + jc] = wbuf[i];
        if (tid < 256) {
            sA[(kq + 0) * 64 + row] = abuf.x;
            sA[(kq + 1) * 64 + row] = abuf.y;
            sA[(kq + 2) * 64 + row] = abuf.z;
            sA[(kq + 3) * 64 + row] = abuf.w;
        }
        __syncthreads();

        if (s + 1 < nsub) {     // prefetch next chunk under compute
            const int kb = k0 + (s + 1) * 16;
            const float* ws = ((kb < II) ? (W1 + (size_t)j * ld1 + kb)
                                         : (W2 + (size_t)j * ld2 + (kb - II))) + kh;
            *(float4*)&wbuf[0] = __ldg((const float4*)ws);
            *(float4*)&wbuf[4] = __ldg((const float4*)(ws + 4));
            if (tid < 256) {
                const float* as = (kb < II) ? (xb + row * xs + kb + kq)
                                            : (cb + row * cs + (kb - II) + kq);
                abuf = __ldcg((const float4*)as);
            }
        }

#pragma unroll
        for (int k = 0; k < 16; k++) {
            const float* pa = sA + k * 64 + bg * 8;
            ulonglong2 a01 = *(const ulonglong2*)pa;        // batches 2p=0,1
            ulonglong2 a23 = *(const ulonglong2*)(pa + 4);  // batches 2p=2,3
            float4 wv = *(const float4*)(sB + k * 256 + cg * 4);
            unsigned long long w0 = splat2(wv.x), w1 = splat2(wv.y);
            unsigned long long w2 = splat2(wv.z), w3 = splat2(wv.w);
            ffma2(acc[0][0], a01.x, w0); ffma2(acc[0][1], a01.y, w0);
            ffma2(acc[0][2], a23.x, w0); ffma2(acc[0][3], a23.y, w0);
            ffma2(acc[1][0], a01.x, w1); ffma2(acc[1][1], a01.y, w1);
            ffma2(acc[1][2], a23.x, w1); ffma2(acc[1][3], a23.y, w1);
            ffma2(acc[2][0], a01.x, w2); ffma2(acc[2][1], a01.y, w2);
            ffma2(acc[2][2], a23.x, w2); ffma2(acc[2][3], a23.y, w2);
            ffma2(acc[3][0], a01.x, w3); ffma2(acc[3][1], a01.y, w3);
            ffma2(acc[3][2], a23.x, w3); ffma2(acc[3][3], a23.y, w3);
        }
        __syncthreads();
    }

    // write partial tile: batch rows bg*8+2p(+1), cols col0 + cg*4 .. +4
#pragma unroll
    for (int p = 0; p < 4; p++) {
        float2 v0 = unpack2(acc[0][p]), v1 = unpack2(acc[1][p]);
        float2 v2 = unpack2(acc[2][p]), v3 = unpack2(acc[3][p]);
        const int b0 = bg * 8 + 2 * p;
        float* d0 = P + (size_t)b0 * NC + col0 + cg * 4;
        float* d1 = d0 + NC;
        *(float4*)d0 = make_float4(v0.x, v1.x, v2.x, v3.x);
        *(float4*)d1 = make_float4(v0.y, v1.y, v2.y, v3.y);
    }
}

// ---------------- gate work (16 CTAs), overlapped with GEMMs -----------------
__device__ __forceinline__ void gate_work(int t, const float* __restrict__ x,
                                          const float* __restrict__ periods,
                                          const float* __restrict__ shifts,
                                          unsigned tgt)
{
    const int gi = blockIdx.x - NGEMM;       // 0..15
    const int tid = threadIdx.x, wid = tid >> 5, lane = tid & 31;

    // pass 1: batch-axis logsumexp for cols [gi*128, gi*128+128)
#pragma unroll
    for (int it = 0; it < 8; it++) {
        const int col = gi * 128 + it * 16 + wid;
        float v0 = __ldcg(&g_XP[lane * IMM + col]);
        float v1 = __ldcg(&g_XP[(lane + 32) * IMM + col]);
        float m = fmaxf(v0, v1);
#pragma unroll
        for (int off = 16; off > 0; off >>= 1)
            m = fmaxf(m, __shfl_xor_sync(0xffffffffu, m, off));
        float s = expf(v0 - m) + expf(v1 - m);
#pragma unroll
        for (int off = 16; off > 0; off >>= 1)
            s += __shfl_xor_sync(0xffffffffu, s, off);
        if (lane == 0) g_lse[col] = m + logf(s);
    }
    // mini-barrier among the 16 gate CTAs
    __syncthreads();
    if (tid == 0) { __threadfence(); g_garr[gi] = tgt; }
    if (gi == 0) {
        if (tid < NGATE) { while ((int)(g_garr[tid] - tgt) < 0) {} }
        __threadfence();
        __syncthreads();
        if (tid == 0) g_ggen = tgt;
        __syncthreads();
    } else {
        if (tid == 0) { while ((int)(g_ggen - tgt) < 0) {} __threadfence(); }
        __syncthreads();
    }
    // pass 2: surprisal -> mp, gate. 512 (b,m) pairs, 2 per warp.
#pragma unroll
    for (int uu = 0; uu < 2; uu++) {
        const int u = gi * 32 + wid * 2 + uu;    // 0..511
        const int b = u >> 3, mo = u & 7;
        float s = 0.f;
#pragma unroll
        for (int i0 = 0; i0 < II; i0 += 32) {
            const int i = i0 + lane;
            s += (__ldcg(&g_XP[b * IMM + mo * II + i]) - __ldcg(&g_lse[mo * II + i]))
                 * __ldg(&x[((size_t)b * TT + t) * II + i]);
        }
#pragma unroll
        for (int off = 16; off > 0; off >>= 1)
            s += __shfl_xor_sync(0xffffffffu, s, off);
        if (lane == 0) {
            const float mp = s * (1.f / (float)II) * __ldg(&periods[mo]);
            g_mp[u] = mp;
            g_gate[u] = (sinf((float)t * mp + __ldg(&shifts[mo])) + 1.f) * 0.5f;
        }
    }
}

// ---------------- persistent kernel ------------------------------------------
__global__ void __launch_bounds__(NT, 1)
cwrnn_kernel(const float* __restrict__ x, const float* __restrict__ W_in,
             const float* __restrict__ b_in, const float* __restrict__ W_h,
             const float* __restrict__ W_ir, const float* __restrict__ b_ir,
             const float* __restrict__ W_hr, const float* __restrict__ periods,
             const float* __restrict__ shifts, float* __restrict__ out)
{
    extern __shared__ float dynsh[];
    const int bid = blockIdx.x, tid = threadIdx.x;
    const int gstep = NBLK * NT;
    float* out_ys = out;
    float* out_hf = out + (size_t)BB * TT * OO;
    float* out_ps = out_hf + BB * OO;

    const unsigned base = g_gen;   // stable across CTAs at launch; monotonic over replays

    // zero carries
    for (int idx = bid * NT + tid; idx < BB * OO; idx += gstep) g_H[idx] = 0.f;
    for (int idx = bid * NT + tid; idx < BB * IMM; idx += gstep) g_XP[idx] = 0.f;
    grid_barrier(base + 1);

    for (int t = 0; t < TT; t++) {
        const unsigned tgtA = base + 2 + 2 * t;
        const unsigned tgtB = base + 3 + 2 * t;
        const float* xb = x + (size_t)t * II;      // A[b][k<II] = xb[b*TT*II + k]

        // ===== phase A ======================================================
        if (bid < NREC) {
            const int nt_ = bid / KSPLIT_REC, ks = bid - nt_ * KSPLIT_REC;
            gemm_unit(xb, TT * II, g_XP, IMM, W_ir, II, W_hr, IMM,
                      nt_ * 256, ks * 192, 12,
                      g_Prec + (size_t)ks * BB * IMM, IMM, dynsh);
        } else if (bid < NGEMM) {
            const int v = bid - NREC;
            const int nt_ = v / KSPLIT_ACT, ks = v - nt_ * KSPLIT_ACT;
            gemm_unit(xb, TT * II, g_H, OO, W_in, II, W_h, OO,
                      nt_ * 256, ks * 160, 10,
                      g_Pact + (size_t)ks * BB * OO, OO, dynsh);
        } else if (bid < NGEMM + NGATE) {
            gate_work(t, x, periods, shifts, tgtA);
        }
        grid_barrier(tgtA);

        // ===== phase B: reduce split-K, tanh, blend, outputs ================
        const int TOTB = BB * IMM + BB * OO;
        for (int idx = bid * NT + tid; idx < TOTB; idx += gstep) {
            if (idx < BB * IMM) {
                const int b = idx >> 11, jj = idx & (IMM - 1);
                float s = __ldg(&b_ir[jj]);
#pragma unroll
                for (int ks = 0; ks < KSPLIT_REC; ks++)
                    s += __ldcg(&g_Prec[((size_t)ks * BB + b) * IMM + jj]);
                g_XP[b * IMM + jj] = tanhf(s);
            } else {
                const int i2 = idx - BB * IMM;
                const int b = i2 >> 10, o = i2 & (OO - 1);
                float s = __ldg(&b_in[o]);
#pragma unroll
                for (int ks = 0; ks < KSPLIT_ACT; ks++)
                    s += __ldcg(&g_Pact[((size_t)ks * BB + b) * OO + o]);
                const float a = tanhf(s);
                const float g = __ldcg(&g_gate[b * MM + (o >> 7)]);
                const float h = g_H[b * OO + o];
                const float y = (1.f - g) * a + g * h;
                out_ys[((size_t)b * TT + t) * OO + o] = y;
                g_H[b * OO + o] = y;
                if (t == TT - 1) out_hf[b * OO + o] = y;
            }
        }
        if (bid == 0) {    // 512 threads cover the 512 mp outputs exactly
            out_ps[((size_t)(tid >> 3) * TT + t) * MM + (tid & 7)] = __ldcg(&g_mp[tid]);
        }
        grid_barrier(tgtB);
    }
}

extern "C" void kernel_launch(void* const* d_in, const int* in_sizes, int n_in,
                              void* d_out, int out_size) {
    (void)in_sizes; (void)n_in; (void)out_size;
    const float* x       = (const float*)d_in[0];
    const float* W_in    = (const float*)d_in[1];
    const float* b_in    = (const float*)d_in[2];
    const float* W_h     = (const float*)d_in[3];
    const float* W_ir    = (const float*)d_in[4];
    const float* b_ir    = (const float*)d_in[5];
    const float* W_hr    = (const float*)d_in[6];
    const float* periods = (const float*)d_in[7];
    const float* shifts  = (const float*)d_in[8];
    float* out = (float*)d_out;

    cwrnn_kernel<<<NBLK, NT, DYN_SMEM>>>(x, W_in, b_in, W_h, W_ir, b_ir, W_hr,
                                         periods, shifts, out);
}